// round 1
// baseline (speedup 1.0000x reference)
#include <cuda_runtime.h>
#include <cstdint>
#include <math.h>

#define IN_D  64
#define H_D   256
#define B_D   128
#define T_D   512
#define GRID  128
#define BLOCK 256

typedef unsigned long long u64;

// ---------------- device globals (scratch; no allocation allowed) ----------------
__device__ float h1_buf[2][B_D * H_D];
__device__ float h2_buf[2][B_D * H_D];
__device__ unsigned bar_count = 0;
__device__ unsigned bar_gen   = 0;

// ---------------- smem layout (bytes) ----------------
// wA2:  [160][32] float2  = 40960   (layer1 weights, K=320 packed by k-pairs)
// wB2:  [256][32] float2  = 65536   (layer2 weights, K=512)
// u2 :  [256][32] float2  = 65536   (input vector staging, k-pair x batch)
// gate: [32][32]  float   = 4096
// biasA/biasB: 32 floats each
#define OFF_WA 0
#define OFF_WB 40960
#define OFF_U  (40960 + 65536)
#define OFF_G  (40960 + 65536 + 65536)
#define OFF_BA (OFF_G + 4096)
#define OFF_BB (OFF_BA + 128)
#define SMEM_BYTES (OFF_BB + 128)   // 176384 bytes

// ---------------- small asm helpers ----------------
__device__ __forceinline__ unsigned ld_acq(const unsigned* p) {
    unsigned v;
    asm volatile("ld.acquire.gpu.u32 %0, [%1];" : "=r"(v) : "l"(p) : "memory");
    return v;
}
__device__ __forceinline__ void st_rel(unsigned* p, unsigned v) {
    asm volatile("st.release.gpu.u32 [%0], %1;" :: "l"(p), "r"(v) : "memory");
}
__device__ __forceinline__ u64 pack2(float x, float y) {
    u64 r; asm("mov.b64 %0, {%1,%2};" : "=l"(r) : "f"(x), "f"(y)); return r;
}
__device__ __forceinline__ float2 unpack2(u64 v) {
    float2 r; asm("mov.b64 {%0,%1}, %2;" : "=f"(r.x), "=f"(r.y) : "l"(v)); return r;
}
__device__ __forceinline__ u64 fma2(u64 a, u64 b, u64 c) {
    u64 d;
    asm("fma.rn.f32x2 %0, %1, %2, %3;" : "=l"(d) : "l"(a), "l"(b), "l"(c));
    return d;
}

// ---------------- grid barrier (all 128 CTAs co-resident) ----------------
__device__ __forceinline__ void gbar(unsigned target) {
    __syncthreads();
    if (threadIdx.x == 0) {
        __threadfence();                       // publish our stores (gpu scope)
        unsigned prev = atomicAdd(&bar_count, 1u);
        if (prev == GRID - 1) {
            bar_count = 0;                     // safe: everyone else is spinning
            st_rel(&bar_gen, target);          // release: orders the reset too
        } else {
            while (ld_acq(&bar_gen) != target) { }
        }
    }
    __syncthreads();
}

// ---------------- GEMM: 32 cols (lane) x 4 batch rows (per warp), K2 k-pairs ----------------
template<int K2>
__device__ __forceinline__ void gemm_phase(const u64* __restrict__ w2,
                                           const u64* __restrict__ u2,
                                           const float* __restrict__ bias,
                                           float* __restrict__ gate,
                                           int warp, int lane) {
    float bv = bias[lane];
    u64 a0 = pack2(bv, 0.f);
    u64 a1 = pack2(bv, 0.f);
    u64 a2 = pack2(bv, 0.f);
    u64 a3 = pack2(bv, 0.f);
    const u64* up = u2 + 4 * warp;
#pragma unroll 8
    for (int k2 = 0; k2 < K2; ++k2) {
        u64 w = w2[k2 * 32 + lane];
        ulonglong2 uab = *(const ulonglong2*)(up + k2 * 32);
        ulonglong2 ucd = *(const ulonglong2*)(up + k2 * 32 + 2);
        a0 = fma2(uab.x, w, a0);
        a1 = fma2(uab.y, w, a1);
        a2 = fma2(ucd.x, w, a2);
        a3 = fma2(ucd.y, w, a3);
    }
    float2 f;
    f = unpack2(a0); gate[(4 * warp + 0) * 32 + lane] = f.x + f.y;
    f = unpack2(a1); gate[(4 * warp + 1) * 32 + lane] = f.x + f.y;
    f = unpack2(a2); gate[(4 * warp + 2) * 32 + lane] = f.x + f.y;
    f = unpack2(a3); gate[(4 * warp + 3) * 32 + lane] = f.x + f.y;
}

// ---------------- sLSTM cell elementwise update (state in registers) ----------------
__device__ __forceinline__ float cell_update(const float* __restrict__ gate,
                                             int be, int je,
                                             float& c, float& m, float& n) {
    float ig = gate[be * 32 +      je];
    float fg = gate[be * 32 +  8 + je];
    float zg = gate[be * 32 + 16 + je];
    float og = gate[be * 32 + 24 + je];
    float z  = tanhf(zg);
    float o  = 1.0f / (1.0f + expf(-og));
    float mt = fmaxf(fg + m, ig);
    float it = expf(ig - mt);
    float ft = expf(fg + m - mt);
    c = ft * c + it * z;
    n = ft * n + it;
    m = mt;
    return o * (c / n);
}

// ---------------- main persistent kernel ----------------
__global__ void __launch_bounds__(BLOCK, 1)
slstm_kernel(const float* __restrict__ x,
             const float* __restrict__ Wxh1, const float* __restrict__ bxh1,
             const float* __restrict__ Whh1, const float* __restrict__ bhh1,
             const float* __restrict__ Wxh2, const float* __restrict__ bxh2,
             const float* __restrict__ Whh2, const float* __restrict__ bhh2,
             const float* __restrict__ W1, const float* __restrict__ b1,
             const float* __restrict__ W2, const float* __restrict__ b2,
             const float* __restrict__ W3, const float* __restrict__ b3,
             float* __restrict__ out) {
    extern __shared__ char smem[];
    float2* wA2  = (float2*)(smem + OFF_WA);
    float2* wB2  = (float2*)(smem + OFF_WB);
    float2* u2   = (float2*)(smem + OFF_U);
    float*  gate = (float*)(smem + OFF_G);
    float*  biasA = (float*)(smem + OFF_BA);
    float*  biasB = (float*)(smem + OFF_BB);

    const int tid  = threadIdx.x;
    const int warp = tid >> 5, lane = tid & 31;
    const int bgroup = blockIdx.x >> 5;   // 0..3   (32 batch rows each)
    const int jgroup = blockIdx.x & 31;   // 0..31  (8 hidden idx each)

    // barrier generation base carries across graph replays (count/gen stable at entry)
    const unsigned base = ld_acq(&bar_gen);

    // ---- stage weights + biases into smem (once) ----
    // smem col c: g = c>>3 (gate), jl = c&7;  global gate row = g*256 + jgroup*8 + jl
    for (int s = tid; s < 32 * 160; s += BLOCK) {
        int c = s & 31, k2 = s >> 5;
        int col = (c >> 3) * 256 + jgroup * 8 + (c & 7);
        int k0 = 2 * k2, k1 = k0 + 1;
        float f0 = (k0 < IN_D) ? Wxh1[col * IN_D + k0] : Whh1[col * H_D + (k0 - IN_D)];
        float f1 = (k1 < IN_D) ? Wxh1[col * IN_D + k1] : Whh1[col * H_D + (k1 - IN_D)];
        wA2[k2 * 32 + c] = make_float2(f0, f1);
    }
    for (int s = tid; s < 32 * 256; s += BLOCK) {
        int c = s & 31, k2 = s >> 5;
        int col = (c >> 3) * 256 + jgroup * 8 + (c & 7);
        int k0 = 2 * k2, k1 = k0 + 1;
        float f0 = (k0 < H_D) ? Wxh2[col * H_D + k0] : Whh2[col * H_D + (k0 - H_D)];
        float f1 = (k1 < H_D) ? Wxh2[col * H_D + k1] : Whh2[col * H_D + (k1 - H_D)];
        wB2[k2 * 32 + c] = make_float2(f0, f1);
    }
    if (tid < 32) {
        int col = (tid >> 3) * 256 + jgroup * 8 + (tid & 7);
        biasA[tid] = bxh1[col] + bhh1[col];
        biasB[tid] = bxh2[col] + bhh2[col];
    }
    __syncthreads();

    // per-thread cell state (one (b,j) element per thread)
    float c1 = 0.f, m1 = 0.f, n1 = 0.f;
    float c2 = 0.f, m2 = 0.f, n2 = 0.f;
    const int be = tid >> 3, je = tid & 7;
    const int bglob_e = bgroup * 32 + be;
    const int jglob   = jgroup * 8 + je;

    unsigned gen = base;

    for (int t = 0; t < T_D; ++t) {
        float*       h1cur = h1_buf[t & 1];
        const float* h1old = h1_buf[(t + 1) & 1];
        float*       h2cur = h2_buf[t & 1];
        const float* h2old = h2_buf[(t + 1) & 1];

        // ---- stage u = [x_t | h1_old] for phase A (K=320 -> 80 float4 per b) ----
        for (int s = tid; s < 32 * 80; s += BLOCK) {
            int b = s / 80, q = s % 80;
            int bglob = bgroup * 32 + b;
            float4 v;
            if (q < 16)      v = *(const float4*)(x + (bglob * T_D + t) * IN_D + q * 4);
            else if (t == 0) v = make_float4(0.f, 0.f, 0.f, 0.f);
            else             v = __ldcg((const float4*)(h1old + bglob * H_D + (q - 16) * 4));
            u2[(2 * q)     * 32 + b] = make_float2(v.x, v.y);
            u2[(2 * q + 1) * 32 + b] = make_float2(v.z, v.w);
        }
        __syncthreads();

        gemm_phase<160>((const u64*)wA2, (const u64*)u2, biasA, gate, warp, lane);
        __syncthreads();

        {
            float h1v = cell_update(gate, be, je, c1, m1, n1);
            h1cur[bglob_e * H_D + jglob] = h1v;
        }
        gbar(++gen);   // all h1 visible chip-wide

        // ---- stage u = [h1_cur | h2_old] for phase B (K=512 -> 128 float4 per b) ----
        for (int s = tid; s < 32 * 128; s += BLOCK) {
            int b = s >> 7, q = s & 127;
            int bglob = bgroup * 32 + b;
            float4 v;
            if (q < 64)      v = __ldcg((const float4*)(h1cur + bglob * H_D + q * 4));
            else if (t == 0) v = make_float4(0.f, 0.f, 0.f, 0.f);
            else             v = __ldcg((const float4*)(h2old + bglob * H_D + (q - 64) * 4));
            u2[(2 * q)     * 32 + b] = make_float2(v.x, v.y);
            u2[(2 * q + 1) * 32 + b] = make_float2(v.z, v.w);
        }
        __syncthreads();

        gemm_phase<256>((const u64*)wB2, (const u64*)u2, biasB, gate, warp, lane);
        __syncthreads();

        {
            float h2v = cell_update(gate, be, je, c2, m2, n2);
            h2cur[bglob_e * H_D + jglob] = h2v;
        }
        gbar(++gen);   // all h2 visible chip-wide
    }

    // ---- head MLP: one batch row per CTA (blockIdx.x = b) ----
    {
        const float* h2fin = h2_buf[(T_D - 1) & 1];   // buf[1]
        int b = blockIdx.x;
        float* hb = (float*)(smem + OFF_U);   // 256
        float* o1 = hb + 256;                 // 128
        float* o2 = o1 + 128;                 // 64
        float* pr = o2 + 64;                  // 64
        for (int i = tid; i < H_D; i += BLOCK) hb[i] = __ldcg(h2fin + b * H_D + i);
        __syncthreads();
        if (tid < 128) {
            const float* w = W1 + tid * H_D;
            float s = b1[tid];
#pragma unroll 4
            for (int k = 0; k < H_D; k += 4) {
                float4 hv = *(const float4*)(hb + k);
                float4 wv = *(const float4*)(w + k);
                s += hv.x * wv.x + hv.y * wv.y + hv.z * wv.z + hv.w * wv.w;
            }
            o1[tid] = fmaxf(s, 0.f);
        }
        __syncthreads();
        if (tid < 64) {
            const float* w = W2 + tid * 128;
            float s = b2[tid];
#pragma unroll 4
            for (int k = 0; k < 128; ++k) s += o1[k] * w[k];
            o2[tid] = fmaxf(s, 0.f);
        }
        __syncthreads();
        if (tid < 64) pr[tid] = o2[tid] * W3[tid];
        __syncthreads();
        if (tid == 0) {
            float s = b3[0];
            for (int k = 0; k < 64; ++k) s += pr[k];
            out[b] = s;
        }
    }
}

extern "C" void kernel_launch(void* const* d_in, const int* in_sizes, int n_in,
                              void* d_out, int out_size) {
    const float* x    = (const float*)d_in[0];
    const float* Wxh1 = (const float*)d_in[1];
    const float* bxh1 = (const float*)d_in[2];
    const float* Whh1 = (const float*)d_in[3];
    const float* bhh1 = (const float*)d_in[4];
    const float* Wxh2 = (const float*)d_in[5];
    const float* bxh2 = (const float*)d_in[6];
    const float* Whh2 = (const float*)d_in[7];
    const float* bhh2 = (const float*)d_in[8];
    const float* W1   = (const float*)d_in[9];
    const float* b1   = (const float*)d_in[10];
    const float* W2   = (const float*)d_in[11];
    const float* b2   = (const float*)d_in[12];
    const float* W3   = (const float*)d_in[13];
    const float* b3   = (const float*)d_in[14];

    cudaFuncSetAttribute(slstm_kernel,
                         cudaFuncAttributeMaxDynamicSharedMemorySize, SMEM_BYTES);
    slstm_kernel<<<GRID, BLOCK, SMEM_BYTES>>>(x, Wxh1, bxh1, Whh1, bhh1,
                                              Wxh2, bxh2, Whh2, bhh2,
                                              W1, b1, W2, b2, W3, b3,
                                              (float*)d_out);
}

// round 3
// speedup vs baseline: 1.2201x; 1.2201x over previous
#include <cuda_runtime.h>
#include <cstdint>
#include <math.h>

#define IN_D  64
#define H_D   256
#define B_D   128
#define T_D   512
#define GRID  128
#define BLOCK 512

typedef unsigned long long u64;

// ---------------- device globals (scratch; no allocation allowed) ----------------
__device__ float h1_buf[2][B_D * H_D];
__device__ float h2_buf[2][B_D * H_D];
__device__ unsigned bar_cnt4[4][32];   // per-bgroup barrier, 128B padded
__device__ unsigned bar_gen4[4][32];
__device__ unsigned gbar_cnt_all;
__device__ unsigned gbar_gen_all;

// ---------------- smem layout (bytes) ----------------
// wA2 : [160][32] float2 = 40960   (layer1 weights, K=320 as k-pairs)
// wB2 : [256][32] float2 = 65536   (layer2 weights, K=512 as k-pairs)
// u2  : [256][32] float2 = 65536   (input vector staging, [k2][batch])
// part: [4][32][32] float2 = 32768 (split-K partials [quarter][b][col])
// gate: [32][32] float = 4096
// biasA/biasB: 32 floats each (padded)
#define OFF_WA 0
#define OFF_WB 40960
#define OFF_U  106496
#define OFF_P  172032
#define OFF_G  204800
#define OFF_BA 208896
#define OFF_BB 209024
#define SMEM_BYTES 209152

// ---------------- asm helpers ----------------
__device__ __forceinline__ unsigned ld_acq(const unsigned* p) {
    unsigned v;
    asm volatile("ld.acquire.gpu.u32 %0, [%1];" : "=r"(v) : "l"(p) : "memory");
    return v;
}
__device__ __forceinline__ void st_rel(unsigned* p, unsigned v) {
    asm volatile("st.release.gpu.u32 [%0], %1;" :: "l"(p), "r"(v) : "memory");
}
__device__ __forceinline__ unsigned atom_add_acqrel(unsigned* p) {
    unsigned v;
    asm volatile("atom.acq_rel.gpu.global.add.u32 %0, [%1], 1;" : "=r"(v) : "l"(p) : "memory");
    return v;
}
__device__ __forceinline__ u64 fma2(u64 a, u64 b, u64 c) {
    u64 d;
    asm("fma.rn.f32x2 %0, %1, %2, %3;" : "=l"(d) : "l"(a), "l"(b), "l"(c));
    return d;
}
__device__ __forceinline__ float tanh_fast(float x) {
    float r;
    asm("tanh.approx.f32 %0, %1;" : "=f"(r) : "f"(x));
    return r;
}

// ---------------- grid barrier ----------------
__device__ __forceinline__ void gbar(unsigned* cnt, unsigned* gen,
                                     unsigned nctas, unsigned target) {
    __syncthreads();
    if (threadIdx.x == 0) {
        unsigned prev = atom_add_acqrel(cnt);
        if (prev == nctas - 1) {
            *cnt = 0;                 // ordered before gen by the release below
            st_rel(gen, target);
        } else {
            while ((int)(ld_acq(gen) - target) < 0) { }
        }
    }
    __syncthreads();
}

// ---------------- split-K GEMM quarter ----------------
// 16 warps = 4 k-quarters x 4 batch-groups(8 rows). lane = column (32 cols/CTA).
template<int K2Q>
__device__ __forceinline__ void gemm_quarter(const u64* __restrict__ w2,
                                             const u64* __restrict__ u2,
                                             u64* __restrict__ part,
                                             int quarter, int g, int lane) {
    u64 a0 = 0, a1 = 0, a2 = 0, a3 = 0, a4 = 0, a5 = 0, a6 = 0, a7 = 0;
    const u64* wp = w2 + quarter * K2Q * 32 + lane;
    const u64* up = u2 + quarter * K2Q * 32 + 8 * g;
#pragma unroll 4
    for (int k = 0; k < K2Q; ++k) {
        u64 w = wp[k * 32];
        ulonglong2 p0 = *(const ulonglong2*)(up + k * 32);
        ulonglong2 p1 = *(const ulonglong2*)(up + k * 32 + 2);
        ulonglong2 p2 = *(const ulonglong2*)(up + k * 32 + 4);
        ulonglong2 p3 = *(const ulonglong2*)(up + k * 32 + 6);
        a0 = fma2(p0.x, w, a0);
        a1 = fma2(p0.y, w, a1);
        a2 = fma2(p1.x, w, a2);
        a3 = fma2(p1.y, w, a3);
        a4 = fma2(p2.x, w, a4);
        a5 = fma2(p2.y, w, a5);
        a6 = fma2(p3.x, w, a6);
        a7 = fma2(p3.y, w, a7);
    }
    u64* pp = part + (quarter * 32 + 8 * g) * 32 + lane;
    pp[0 * 32] = a0;  pp[1 * 32] = a1;  pp[2 * 32] = a2;  pp[3 * 32] = a3;
    pp[4 * 32] = a4;  pp[5 * 32] = a5;  pp[6 * 32] = a6;  pp[7 * 32] = a7;
}

// reduce 4 partials + bias -> gate[b][c]
__device__ __forceinline__ void reduce_gate(const float2* __restrict__ part,
                                            const float* __restrict__ bias,
                                            float* __restrict__ gate, int tid) {
#pragma unroll
    for (int e = tid; e < 1024; e += BLOCK) {
        int b = e >> 5, c = e & 31;
        float2 s0 = part[(0 * 32 + b) * 32 + c];
        float2 s1 = part[(1 * 32 + b) * 32 + c];
        float2 s2 = part[(2 * 32 + b) * 32 + c];
        float2 s3 = part[(3 * 32 + b) * 32 + c];
        gate[b * 32 + c] = ((s0.x + s1.x) + (s2.x + s3.x))
                         + ((s0.y + s1.y) + (s2.y + s3.y)) + bias[c];
    }
}

// ---------------- sLSTM cell elementwise update (state in registers) ----------------
__device__ __forceinline__ float cell_update(const float* __restrict__ gate,
                                             int be, int je,
                                             float& c, float& m, float& n) {
    float ig = gate[be * 32 +      je];
    float fg = gate[be * 32 +  8 + je];
    float zg = gate[be * 32 + 16 + je];
    float og = gate[be * 32 + 24 + je];
    float z  = tanh_fast(zg);
    float o  = __fdividef(1.0f, 1.0f + __expf(-og));
    float mt = fmaxf(fg + m, ig);
    float it = __expf(ig - mt);
    float ft = __expf(fg + m - mt);
    c = ft * c + it * z;
    n = ft * n + it;
    m = mt;
    return o * __fdividef(c, n);
}

// ---------------- main persistent kernel ----------------
__global__ void __launch_bounds__(BLOCK, 1)
slstm_kernel(const float* __restrict__ x,
             const float* __restrict__ Wxh1, const float* __restrict__ bxh1,
             const float* __restrict__ Whh1, const float* __restrict__ bhh1,
             const float* __restrict__ Wxh2, const float* __restrict__ bxh2,
             const float* __restrict__ Whh2, const float* __restrict__ bhh2,
             const float* __restrict__ W1, const float* __restrict__ b1,
             const float* __restrict__ W2, const float* __restrict__ b2,
             const float* __restrict__ W3, const float* __restrict__ b3,
             float* __restrict__ out) {
    extern __shared__ char smem[];
    float2* wA2   = (float2*)(smem + OFF_WA);
    float2* wB2   = (float2*)(smem + OFF_WB);
    float2* u2    = (float2*)(smem + OFF_U);
    u64*    partW = (u64*)(smem + OFF_P);
    float2* partR = (float2*)(smem + OFF_P);
    float*  gate  = (float*)(smem + OFF_G);
    float*  biasA = (float*)(smem + OFF_BA);
    float*  biasB = (float*)(smem + OFF_BB);

    const int tid  = threadIdx.x;
    const int warp = tid >> 5, lane = tid & 31;
    const int quarter = warp >> 2, g = warp & 3;
    const int bgroup = blockIdx.x >> 5;   // 0..3   (32 batch rows each)
    const int jgroup = blockIdx.x & 31;   // 0..31  (8 hidden idx each)

    unsigned* my_cnt = &bar_cnt4[bgroup][0];
    unsigned* my_gen = &bar_gen4[bgroup][0];
    const unsigned base_g   = ld_acq(my_gen);       // stable across graph replays
    const unsigned base_all = ld_acq(&gbar_gen_all);

    // ---- stage weights + biases into smem (once) ----
    for (int s = tid; s < 32 * 160; s += BLOCK) {
        int c = s & 31, k2 = s >> 5;
        int col = (c >> 3) * 256 + jgroup * 8 + (c & 7);
        int k0 = 2 * k2, k1 = k0 + 1;
        float f0 = (k0 < IN_D) ? Wxh1[col * IN_D + k0] : Whh1[col * H_D + (k0 - IN_D)];
        float f1 = (k1 < IN_D) ? Wxh1[col * IN_D + k1] : Whh1[col * H_D + (k1 - IN_D)];
        wA2[k2 * 32 + c] = make_float2(f0, f1);
    }
    for (int s = tid; s < 32 * 256; s += BLOCK) {
        int c = s & 31, k2 = s >> 5;
        int col = (c >> 3) * 256 + jgroup * 8 + (c & 7);
        int k0 = 2 * k2, k1 = k0 + 1;
        float f0 = (k0 < H_D) ? Wxh2[col * H_D + k0] : Whh2[col * H_D + (k0 - H_D)];
        float f1 = (k1 < H_D) ? Wxh2[col * H_D + k1] : Whh2[col * H_D + (k1 - H_D)];
        wB2[k2 * 32 + c] = make_float2(f0, f1);
    }
    if (tid < 32) {
        int col = (tid >> 3) * 256 + jgroup * 8 + (tid & 7);
        biasA[tid] = bxh1[col] + bhh1[col];
        biasB[tid] = bxh2[col] + bhh2[col];
    }
    __syncthreads();

    // per-thread cell state (tid<256: one (b,j) element per thread)
    float c1 = 0.f, m1 = 0.f, n1 = 0.f;
    float c2 = 0.f, m2 = 0.f, n2 = 0.f;
    const int be = tid >> 3, je = tid & 7;                // valid for tid<256
    const int bglob_e = bgroup * 32 + (tid >> 3);
    const int jglob   = jgroup * 8 + je;

    // staging thread mapping: sb = batch row, sq = lane-of-16
    const int sb = tid >> 4, sq = tid & 15;
    const int bglobs = bgroup * 32 + sb;

    for (int t = 0; t < T_D; ++t) {
        float*       h1cur = h1_buf[t & 1];
        const float* h1old = h1_buf[(t + 1) & 1];
        float*       h2cur = h2_buf[t & 1];
        const float* h2old = h2_buf[(t + 1) & 1];

        // ---- stage u = [x_t | h1_old] (K=320 -> 80 float4 per b; 5 per thread) ----
        {
            const float* xrow = x + (bglobs * T_D + t) * IN_D;
            // i = 0: q = sq < 16 -> x
            {
                float4 v = *(const float4*)(xrow + sq * 4);
                u2[(2 * sq) * 32 + sb]     = make_float2(v.x, v.y);
                u2[(2 * sq + 1) * 32 + sb] = make_float2(v.z, v.w);
            }
#pragma unroll
            for (int i = 1; i < 5; ++i) {
                int q = sq + 16 * i;
                float4 v = (t == 0) ? make_float4(0.f, 0.f, 0.f, 0.f)
                                    : __ldcg((const float4*)(h1old + bglobs * H_D + (q - 16) * 4));
                u2[(2 * q) * 32 + sb]     = make_float2(v.x, v.y);
                u2[(2 * q + 1) * 32 + sb] = make_float2(v.z, v.w);
            }
        }
        __syncthreads();

        gemm_quarter<40>((const u64*)wA2, (const u64*)u2, partW, quarter, g, lane);
        __syncthreads();
        reduce_gate(partR, biasA, gate, tid);
        __syncthreads();

        if (tid < 256) {
            float h1v = cell_update(gate, be, je, c1, m1, n1);
            h1cur[bglob_e * H_D + jglob] = h1v;
        }
        gbar(my_cnt, my_gen, 32u, base_g + (unsigned)t + 1u);   // one barrier per step

        // ---- stage u = [h1_cur | h2_old] (K=512 -> 128 float4 per b; 8 per thread) ----
        {
#pragma unroll
            for (int i = 0; i < 4; ++i) {
                int q = sq + 16 * i;
                float4 v = __ldcg((const float4*)(h1cur + bglobs * H_D + q * 4));
                u2[(2 * q) * 32 + sb]     = make_float2(v.x, v.y);
                u2[(2 * q + 1) * 32 + sb] = make_float2(v.z, v.w);
            }
#pragma unroll
            for (int i = 4; i < 8; ++i) {
                int q = sq + 16 * i;
                float4 v = (t == 0) ? make_float4(0.f, 0.f, 0.f, 0.f)
                                    : __ldcg((const float4*)(h2old + bglobs * H_D + (q - 64) * 4));
                u2[(2 * q) * 32 + sb]     = make_float2(v.x, v.y);
                u2[(2 * q + 1) * 32 + sb] = make_float2(v.z, v.w);
            }
        }
        __syncthreads();

        gemm_quarter<64>((const u64*)wB2, (const u64*)u2, partW, quarter, g, lane);
        __syncthreads();
        reduce_gate(partR, biasB, gate, tid);
        __syncthreads();

        if (tid < 256) {
            float h2v = cell_update(gate, be, je, c2, m2, n2);
            h2cur[bglob_e * H_D + jglob] = h2v;
        }
        // no second barrier: next step's group barrier provides the ordering
    }

    // all 128 CTAs must see final h2 before the head MLP (cross-bgroup reads)
    gbar(&gbar_cnt_all, &gbar_gen_all, (unsigned)GRID, base_all + 1u);

    // ---- head MLP: one batch row per CTA (blockIdx.x = b) ----
    {
        const float* h2fin = h2_buf[(T_D - 1) & 1];   // buf[1]
        int b = blockIdx.x;
        float* hb = (float*)(smem + OFF_U);   // 256
        float* o1 = hb + 256;                 // 128
        float* o2 = o1 + 128;                 // 64
        float* pr = o2 + 64;                  // 64
        for (int i = tid; i < H_D; i += BLOCK) hb[i] = __ldcg(h2fin + b * H_D + i);
        __syncthreads();
        if (tid < 128) {
            const float* w = W1 + tid * H_D;
            float s = b1[tid];
#pragma unroll 4
            for (int k = 0; k < H_D; k += 4) {
                float4 hv = *(const float4*)(hb + k);
                float4 wv = *(const float4*)(w + k);
                s += hv.x * wv.x + hv.y * wv.y + hv.z * wv.z + hv.w * wv.w;
            }
            o1[tid] = fmaxf(s, 0.f);
        }
        __syncthreads();
        if (tid < 64) {
            const float* w = W2 + tid * 128;
            float s = b2[tid];
#pragma unroll 4
            for (int k = 0; k < 128; ++k) s += o1[k] * w[k];
            o2[tid] = fmaxf(s, 0.f);
        }
        __syncthreads();
        if (tid < 64) pr[tid] = o2[tid] * W3[tid];
        __syncthreads();
        if (tid == 0) {
            float s = b3[0];
            for (int k = 0; k < 64; ++k) s += pr[k];
            out[b] = s;
        }
    }
}

extern "C" void kernel_launch(void* const* d_in, const int* in_sizes, int n_in,
                              void* d_out, int out_size) {
    const float* x    = (const float*)d_in[0];
    const float* Wxh1 = (const float*)d_in[1];
    const float* bxh1 = (const float*)d_in[2];
    const float* Whh1 = (const float*)d_in[3];
    const float* bhh1 = (const float*)d_in[4];
    const float* Wxh2 = (const float*)d_in[5];
    const float* bxh2 = (const float*)d_in[6];
    const float* Whh2 = (const float*)d_in[7];
    const float* bhh2 = (const float*)d_in[8];
    const float* W1   = (const float*)d_in[9];
    const float* b1   = (const float*)d_in[10];
    const float* W2   = (const float*)d_in[11];
    const float* b2   = (const float*)d_in[12];
    const float* W3   = (const float*)d_in[13];
    const float* b3   = (const float*)d_in[14];

    cudaFuncSetAttribute(slstm_kernel,
                         cudaFuncAttributeMaxDynamicSharedMemorySize, SMEM_BYTES);
    slstm_kernel<<<GRID, BLOCK, SMEM_BYTES>>>(x, Wxh1, bxh1, Whh1, bhh1,
                                              Wxh2, bxh2, Whh2, bhh2,
                                              W1, b1, W2, b2, W3, b3,
                                              (float*)d_out);
}

// round 6
// speedup vs baseline: 1.8780x; 1.5392x over previous
#include <cuda_runtime.h>
#include <cstdint>
#include <math.h>

#define IN_D  64
#define H_D   256
#define B_D   128
#define T_D   512
#define GRID  128
#define BLOCK 512

typedef unsigned long long u64;

// ---------------- device globals ----------------
__device__ float h1_buf[2][B_D * H_D];
__device__ float h2_buf[2][B_D * H_D];
__device__ unsigned bar_cnt4[4][32];   // per-bgroup barrier, padded
__device__ unsigned bar_gen4[4][32];
__device__ unsigned gbar_cnt_all;
__device__ unsigned gbar_gen_all;

// ---------------- smem layout (bytes) ----------------
// wA4 : [80][32]  float4 = 40960   (layer1 weights, K=320 as k-quads, col-minor)
// wB4 : [128][32] float4 = 65536   (layer2 weights, K=512 as k-quads)
// u4  : [128][33] float4 = 67584   (staging, [k-quad][batch], stride 33 = odd -> conflict-free)
// part: [8][32][32] f32  = 32768   (split-K partials [slice][b][col])
// gate: [32][32] f32     = 4096
// biasA/biasB
#define U_STRIDE 33
#define OFF_WA 0
#define OFF_WB 40960
#define OFF_U  106496
#define OFF_P  174080
#define OFF_G  206848
#define OFF_BA 210944
#define OFF_BB 211072
#define SMEM_BYTES 211200

// ---------------- asm helpers ----------------
__device__ __forceinline__ unsigned ld_acq(const unsigned* p) {
    unsigned v;
    asm volatile("ld.acquire.gpu.u32 %0, [%1];" : "=r"(v) : "l"(p) : "memory");
    return v;
}
__device__ __forceinline__ void st_rel(unsigned* p, unsigned v) {
    asm volatile("st.release.gpu.u32 [%0], %1;" :: "l"(p), "r"(v) : "memory");
}
__device__ __forceinline__ unsigned atom_add_acqrel(unsigned* p) {
    unsigned v;
    asm volatile("atom.acq_rel.gpu.global.add.u32 %0, [%1], 1;" : "=r"(v) : "l"(p) : "memory");
    return v;
}
__device__ __forceinline__ u64 fma2(u64 a, u64 b, u64 c) {
    u64 d;
    asm("fma.rn.f32x2 %0, %1, %2, %3;" : "=l"(d) : "l"(a), "l"(b), "l"(c));
    return d;
}
__device__ __forceinline__ float2 unpack2(u64 v) {
    float2 r; asm("mov.b64 {%0,%1}, %2;" : "=f"(r.x), "=f"(r.y) : "l"(v)); return r;
}
__device__ __forceinline__ float tanh_fast(float x) {
    float r;
    asm("tanh.approx.f32 %0, %1;" : "=f"(r) : "f"(x));
    return r;
}

// ---------------- grid barrier ----------------
__device__ __forceinline__ void gbar(unsigned* cnt, unsigned* gen,
                                     unsigned nctas, unsigned target) {
    __syncthreads();
    if (threadIdx.x == 0) {
        unsigned prev = atom_add_acqrel(cnt);
        if (prev == nctas - 1) {
            *cnt = 0;
            st_rel(gen, target);
        } else {
            while ((int)(ld_acq(gen) - target) < 0) { }
        }
    }
    __syncthreads();
}

// ---------------- split-K(8) GEMM slice: 16 warps = 8 k-slices x 2 bgroups(16 rows) ----------------
// lane = column. Per q-iter: w = 2 k-pairs (LDS.128), u = 16 batch float4 broadcasts.
template<int K4S>
__device__ __forceinline__ void gemm_slice(const float4* __restrict__ w4,
                                           const float4* __restrict__ u4,
                                           float* __restrict__ part,
                                           int slice, int bg, int lane) {
    u64 acc[16];
#pragma unroll
    for (int r = 0; r < 16; ++r) acc[r] = 0;

    const ulonglong2* wp = (const ulonglong2*)(w4 + slice * K4S * 32 + lane);
    const float4*     up = u4 + slice * K4S * U_STRIDE + 16 * bg;
#pragma unroll 2
    for (int q = 0; q < K4S; ++q) {
        ulonglong2 w = wp[q * 32];
        const ulonglong2* ub = (const ulonglong2*)(up + q * U_STRIDE);
#pragma unroll
        for (int r = 0; r < 16; ++r) {
            ulonglong2 uv = ub[r];
            acc[r] = fma2(uv.x, w.x, acc[r]);
            acc[r] = fma2(uv.y, w.y, acc[r]);
        }
    }
    float* pp = part + (slice * 32 + 16 * bg) * 32 + lane;
#pragma unroll
    for (int r = 0; r < 16; ++r) {
        float2 f = unpack2(acc[r]);
        pp[r * 32] = f.x + f.y;
    }
}

// reduce 8 partials + bias -> gate[b][c]
__device__ __forceinline__ void reduce_gate(const float* __restrict__ part,
                                            const float* __restrict__ bias,
                                            float* __restrict__ gate, int tid) {
#pragma unroll
    for (int e = tid; e < 1024; e += BLOCK) {
        int b = e >> 5, c = e & 31;
        const float* p = part + b * 32 + c;
        float s = bias[c];
#pragma unroll
        for (int sl = 0; sl < 8; ++sl) s += p[sl * 1024];
        gate[b * 32 + c] = s;
    }
}

// ---------------- sLSTM cell elementwise update ----------------
__device__ __forceinline__ float cell_update(const float* __restrict__ gate,
                                             int be, int je,
                                             float& c, float& m, float& n) {
    float ig = gate[be * 32 +      je];
    float fg = gate[be * 32 +  8 + je];
    float zg = gate[be * 32 + 16 + je];
    float og = gate[be * 32 + 24 + je];
    float z  = tanh_fast(zg);
    float o  = __fdividef(1.0f, 1.0f + __expf(-og));
    float mt = fmaxf(fg + m, ig);
    float it = __expf(ig - mt);
    float ft = __expf(fg + m - mt);
    c = ft * c + it * z;
    n = ft * n + it;
    m = mt;
    return o * __fdividef(c, n);
}

// ---------------- main persistent kernel ----------------
__global__ void __launch_bounds__(BLOCK, 1)
slstm_kernel(const float* __restrict__ x,
             const float* __restrict__ Wxh1, const float* __restrict__ bxh1,
             const float* __restrict__ Whh1, const float* __restrict__ bhh1,
             const float* __restrict__ Wxh2, const float* __restrict__ bxh2,
             const float* __restrict__ Whh2, const float* __restrict__ bhh2,
             const float* __restrict__ W1, const float* __restrict__ b1,
             const float* __restrict__ W2, const float* __restrict__ b2,
             const float* __restrict__ W3, const float* __restrict__ b3,
             float* __restrict__ out) {
    extern __shared__ char smem[];
    float4* wA4   = (float4*)(smem + OFF_WA);
    float4* wB4   = (float4*)(smem + OFF_WB);
    float4* u4    = (float4*)(smem + OFF_U);
    float*  part  = (float*)(smem + OFF_P);
    float*  gate  = (float*)(smem + OFF_G);
    float*  biasA = (float*)(smem + OFF_BA);
    float*  biasB = (float*)(smem + OFF_BB);

    const int tid  = threadIdx.x;
    const int warp = tid >> 5, lane = tid & 31;
    const int slice = warp >> 1, bg = warp & 1;
    const int bgroup = blockIdx.x >> 5;   // 0..3  (32 batch rows each)
    const int jgroup = blockIdx.x & 31;   // 0..31 (8 hidden idx each)

    unsigned* my_cnt = &bar_cnt4[bgroup][0];
    unsigned* my_gen = &bar_gen4[bgroup][0];
    const unsigned base_g   = ld_acq(my_gen);
    const unsigned base_all = ld_acq(&gbar_gen_all);

    // ---- stage weights (k-quad major) + biases ----
    // smem col c: gate g = c>>3, jl = c&7 -> global row col = g*256 + jgroup*8 + jl
    for (int s = tid; s < 80 * 32; s += BLOCK) {
        int c = s & 31, q = s >> 5;
        int col = (c >> 3) * 256 + jgroup * 8 + (c & 7);
        int k0 = 4 * q;
        float4 v;
        if (k0 < IN_D) v = *(const float4*)(Wxh1 + col * IN_D + k0);
        else           v = *(const float4*)(Whh1 + col * H_D + (k0 - IN_D));
        wA4[q * 32 + c] = v;
    }
    for (int s = tid; s < 128 * 32; s += BLOCK) {
        int c = s & 31, q = s >> 5;
        int col = (c >> 3) * 256 + jgroup * 8 + (c & 7);
        int k0 = 4 * q;
        float4 v;
        if (k0 < H_D) v = *(const float4*)(Wxh2 + col * H_D + k0);
        else          v = *(const float4*)(Whh2 + col * H_D + (k0 - H_D));
        wB4[q * 32 + c] = v;
    }
    if (tid < 32) {
        int col = (tid >> 3) * 256 + jgroup * 8 + (tid & 7);
        biasA[tid] = bxh1[col] + bhh1[col];
        biasB[tid] = bxh2[col] + bhh2[col];
    }
    __syncthreads();

    // per-thread cell state (tid<256)
    float c1 = 0.f, m1 = 0.f, n1 = 0.f;
    float c2 = 0.f, m2 = 0.f, n2 = 0.f;
    const int be = tid >> 3, je = tid & 7;
    const int bglob_e = bgroup * 32 + be;
    const int jglob   = jgroup * 8 + je;

    // staging mapping: sb = batch row (0..31), sq = 0..15
    const int sb = tid >> 4, sq = tid & 15;
    const int bglobs = bgroup * 32 + sb;
    const float4 zero4 = make_float4(0.f, 0.f, 0.f, 0.f);

    for (int t = 0; t < T_D; ++t) {
        float*       h1cur = h1_buf[t & 1];
        const float* h1old = h1_buf[(t + 1) & 1];
        float*       h2cur = h2_buf[t & 1];
        const float* h2old = h2_buf[(t + 1) & 1];

        // ---- stage u = [x_t | h1_old]  (80 k-quads) ----
        {
            const float* xrow = x + (bglobs * T_D + t) * IN_D;
            float4 v0 = *(const float4*)(xrow + sq * 4);
            u4[sq * U_STRIDE + sb] = v0;
#pragma unroll
            for (int i = 1; i < 5; ++i) {
                int q = sq + 16 * i;
                float4 v = (t == 0) ? zero4
                         : __ldcg((const float4*)(h1old + bglobs * H_D + (q - 16) * 4));
                u4[q * U_STRIDE + sb] = v;
            }
        }
        __syncthreads();

        gemm_slice<10>(wA4, u4, part, slice, bg, lane);
        __syncthreads();
        reduce_gate(part, biasA, gate, tid);
        __syncthreads();

        if (tid < 256) {
            float h1v = cell_update(gate, be, je, c1, m1, n1);
            h1cur[bglob_e * H_D + jglob] = h1v;
        }
        gbar(my_cnt, my_gen, 32u, base_g + (unsigned)t + 1u);   // one barrier per step

        // ---- stage u = [h1_cur | h2_old]  (128 k-quads) ----
        {
#pragma unroll
            for (int i = 0; i < 4; ++i) {
                int q = sq + 16 * i;
                float4 v = __ldcg((const float4*)(h1cur + bglobs * H_D + q * 4));
                u4[q * U_STRIDE + sb] = v;
            }
#pragma unroll
            for (int i = 4; i < 8; ++i) {
                int q = sq + 16 * i;
                float4 v = (t == 0) ? zero4
                         : __ldcg((const float4*)(h2old + bglobs * H_D + (q - 64) * 4));
                u4[q * U_STRIDE + sb] = v;
            }
        }
        __syncthreads();

        gemm_slice<16>(wB4, u4, part, slice, bg, lane);
        __syncthreads();
        reduce_gate(part, biasB, gate, tid);
        __syncthreads();

        if (tid < 256) {
            float h2v = cell_update(gate, be, je, c2, m2, n2);
            h2cur[bglob_e * H_D + jglob] = h2v;
        }
        // next step's group barrier provides the ordering for h2
    }

    gbar(&gbar_cnt_all, &gbar_gen_all, (unsigned)GRID, base_all + 1u);

    // ---- head MLP: one batch row per CTA ----
    {
        const float* h2fin = h2_buf[(T_D - 1) & 1];
        int b = blockIdx.x;
        float* hb = (float*)(smem + OFF_U);
        float* o1 = hb + 256;
        float* o2 = o1 + 128;
        float* pr = o2 + 64;
        for (int i = tid; i < H_D; i += BLOCK) hb[i] = __ldcg(h2fin + b * H_D + i);
        __syncthreads();
        if (tid < 128) {
            const float* w = W1 + tid * H_D;
            float s = b1[tid];
#pragma unroll 4
            for (int k = 0; k < H_D; k += 4) {
                float4 hv = *(const float4*)(hb + k);
                float4 wv = *(const float4*)(w + k);
                s += hv.x * wv.x + hv.y * wv.y + hv.z * wv.z + hv.w * wv.w;
            }
            o1[tid] = fmaxf(s, 0.f);
        }
        __syncthreads();
        if (tid < 64) {
            const float* w = W2 + tid * 128;
            float s = b2[tid];
#pragma unroll 4
            for (int k = 0; k < 128; ++k) s += o1[k] * w[k];
            o2[tid] = fmaxf(s, 0.f);
        }
        __syncthreads();
        if (tid < 64) pr[tid] = o2[tid] * W3[tid];
        __syncthreads();
        if (tid == 0) {
            float s = b3[0];
            for (int k = 0; k < 64; ++k) s += pr[k];
            out[b] = s;
        }
    }
}

extern "C" void kernel_launch(void* const* d_in, const int* in_sizes, int n_in,
                              void* d_out, int out_size) {
    const float* x    = (const float*)d_in[0];
    const float* Wxh1 = (const float*)d_in[1];
    const float* bxh1 = (const float*)d_in[2];
    const float* Whh1 = (const float*)d_in[3];
    const float* bhh1 = (const float*)d_in[4];
    const float* Wxh2 = (const float*)d_in[5];
    const float* bxh2 = (const float*)d_in[6];
    const float* Whh2 = (const float*)d_in[7];
    const float* bhh2 = (const float*)d_in[8];
    const float* W1   = (const float*)d_in[9];
    const float* b1   = (const float*)d_in[10];
    const float* W2   = (const float*)d_in[11];
    const float* b2   = (const float*)d_in[12];
    const float* W3   = (const float*)d_in[13];
    const float* b3   = (const float*)d_in[14];

    cudaFuncSetAttribute(slstm_kernel,
                         cudaFuncAttributeMaxDynamicSharedMemorySize, SMEM_BYTES);
    slstm_kernel<<<GRID, BLOCK, SMEM_BYTES>>>(x, Wxh1, bxh1, Whh1, bhh1,
                                              Wxh2, bxh2, Whh2, bhh2,
                                              W1, b1, W2, b2, W3, b3,
                                              (float*)d_out);
}

// round 8
// speedup vs baseline: 2.3006x; 1.2250x over previous
#include <cuda_runtime.h>
#include <cstdint>
#include <math.h>

#define IN_D  64
#define H_D   256
#define B_D   128
#define T_D   512
#define GRID  128
#define BLOCK 512

typedef unsigned long long u64;

// ---------------- device globals ----------------
__device__ float h1_buf[2][B_D * H_D];
__device__ float h2_buf[2][B_D * H_D];
__device__ unsigned bar_cnt4[4][32];
__device__ unsigned bar_gen4[4][32];
__device__ unsigned gbar_cnt_all;
__device__ unsigned gbar_gen_all;

// ---------------- smem layout ----------------
// wA : [32 c][162 k2] u64 = 41472   (layer1, K=320 -> 160 k-pairs, stride 162 == 2 mod 16)
// wB : [32 c][258 k2] u64 = 66048   (layer2, K=512 -> 256 k-pairs, stride 258)
// u  : [32 b][258 k2] u64 = 66048   (staging, stride 258)
// part:[8 sl][32 b][40 c] f32 = 40960  (stride 40 -> coalesced float2 stores)
// gate:[32][32] f32 = 4096
#define WA_S2 81     /* wA row stride in ulonglong2 units (162/2) */
#define WB_S2 129    /* wB/u row stride in ulonglong2 units (258/2) */
#define OFF_WA 0
#define OFF_WB 41472
#define OFF_U  107520
#define OFF_P  173568
#define OFF_G  214528
#define OFF_BA 218624
#define OFF_BB 218752
#define SMEM_BYTES 218880

// ---------------- asm helpers ----------------
__device__ __forceinline__ unsigned ld_acq(const unsigned* p) {
    unsigned v;
    asm volatile("ld.acquire.gpu.u32 %0, [%1];" : "=r"(v) : "l"(p) : "memory");
    return v;
}
__device__ __forceinline__ void st_rel(unsigned* p, unsigned v) {
    asm volatile("st.release.gpu.u32 [%0], %1;" :: "l"(p), "r"(v) : "memory");
}
__device__ __forceinline__ unsigned atom_add_acqrel(unsigned* p) {
    unsigned v;
    asm volatile("atom.acq_rel.gpu.global.add.u32 %0, [%1], 1;" : "=r"(v) : "l"(p) : "memory");
    return v;
}
__device__ __forceinline__ u64 fma2(u64 a, u64 b, u64 c) {
    u64 d;
    asm("fma.rn.f32x2 %0, %1, %2, %3;" : "=l"(d) : "l"(a), "l"(b), "l"(c));
    return d;
}
__device__ __forceinline__ float2 unpack2(u64 v) {
    float2 r; asm("mov.b64 {%0,%1}, %2;" : "=f"(r.x), "=f"(r.y) : "l"(v)); return r;
}
__device__ __forceinline__ float tanh_fast(float x) {
    float r;
    asm("tanh.approx.f32 %0, %1;" : "=f"(r) : "f"(x));
    return r;
}

// ---------------- grid barrier ----------------
__device__ __forceinline__ void gbar(unsigned* cnt, unsigned* gen,
                                     unsigned nctas, unsigned target) {
    __syncthreads();
    if (threadIdx.x == 0) {
        unsigned prev = atom_add_acqrel(cnt);
        if (prev == nctas - 1) {
            *cnt = 0;
            st_rel(gen, target);
        } else {
            while ((int)(ld_acq(gen) - target) < 0) { }
        }
    }
    __syncthreads();
}

// ---------------- register-tiled GEMM ----------------
// 16 warps = 8 k-slices x 2 c-halves. Lanes (bq 0..7, cq 0..3).
// Thread tile 4b x 4c: b in {bq+8r}, c in {cg*16 + 2cq + {0,1,8,9}}.
// u[b][k2] stride 258 u64; w[c][k2] stride 2*WS2 u64. k-pairs packed in f32x2.
template<int K2S, int WS2>
__device__ __forceinline__ void gemm_tile(const u64* __restrict__ wsm,
                                          const u64* __restrict__ usm,
                                          float* __restrict__ part,
                                          int sl, int cg, int lane) {
    const int bq = lane & 7, cq = (lane >> 3) & 3;
    const int k2h = (sl * K2S) >> 1;   // slice base in ulonglong2 units
    const ulonglong2* up = (const ulonglong2*)usm + bq * WB_S2 + k2h;
    const ulonglong2* wp = (const ulonglong2*)wsm + (cg * 16 + 2 * cq) * WS2 + k2h;

    u64 acc[4][4];
#pragma unroll
    for (int r = 0; r < 4; ++r)
#pragma unroll
        for (int j = 0; j < 4; ++j) acc[r][j] = 0;

#pragma unroll 2
    for (int k = 0; k < K2S / 2; ++k) {
        ulonglong2 uf0 = up[k];
        ulonglong2 uf1 = up[k +  8 * WB_S2];
        ulonglong2 uf2 = up[k + 16 * WB_S2];
        ulonglong2 uf3 = up[k + 24 * WB_S2];
        ulonglong2 wf0 = wp[k];
        ulonglong2 wf1 = wp[k + WS2];
        ulonglong2 wf2 = wp[k + 8 * WS2];
        ulonglong2 wf3 = wp[k + 9 * WS2];
#pragma unroll
        for (int r = 0; r < 4; ++r) {
            ulonglong2 uv = (r == 0) ? uf0 : (r == 1) ? uf1 : (r == 2) ? uf2 : uf3;
            acc[r][0] = fma2(uv.x, wf0.x, acc[r][0]);
            acc[r][0] = fma2(uv.y, wf0.y, acc[r][0]);
            acc[r][1] = fma2(uv.x, wf1.x, acc[r][1]);
            acc[r][1] = fma2(uv.y, wf1.y, acc[r][1]);
            acc[r][2] = fma2(uv.x, wf2.x, acc[r][2]);
            acc[r][2] = fma2(uv.y, wf2.y, acc[r][2]);
            acc[r][3] = fma2(uv.x, wf3.x, acc[r][3]);
            acc[r][3] = fma2(uv.y, wf3.y, acc[r][3]);
        }
    }

    float* pp = part + sl * 1280 + bq * 40 + cg * 16 + 2 * cq;
#pragma unroll
    for (int r = 0; r < 4; ++r) {
        float2 a = unpack2(acc[r][0]);
        float2 b = unpack2(acc[r][1]);
        float2 c = unpack2(acc[r][2]);
        float2 d = unpack2(acc[r][3]);
        *(float2*)(pp + 320 * r)     = make_float2(a.x + a.y, b.x + b.y);
        *(float2*)(pp + 320 * r + 8) = make_float2(c.x + c.y, d.x + d.y);
    }
}

// reduce 8 slice-partials + bias -> gate[b][c]
__device__ __forceinline__ void reduce_gate(const float* __restrict__ part,
                                            const float* __restrict__ bias,
                                            float* __restrict__ gate, int tid) {
#pragma unroll
    for (int e = tid; e < 1024; e += BLOCK) {
        int b = e >> 5, c = e & 31;
        const float* p = part + b * 40 + c;
        float s = bias[c];
#pragma unroll
        for (int sl = 0; sl < 8; ++sl) s += p[sl * 1280];
        gate[b * 32 + c] = s;
    }
}

// ---------------- sLSTM cell elementwise update ----------------
__device__ __forceinline__ float cell_update(const float* __restrict__ gate,
                                             int be, int je,
                                             float& c, float& m, float& n) {
    float ig = gate[be * 32 +      je];
    float fg = gate[be * 32 +  8 + je];
    float zg = gate[be * 32 + 16 + je];
    float og = gate[be * 32 + 24 + je];
    float z  = tanh_fast(zg);
    float o  = __fdividef(1.0f, 1.0f + __expf(-og));
    float mt = fmaxf(fg + m, ig);
    float it = __expf(ig - mt);
    float ft = __expf(fg + m - mt);
    c = ft * c + it * z;
    n = ft * n + it;
    m = mt;
    return o * __fdividef(c, n);
}

// ---------------- main persistent kernel ----------------
__global__ void __launch_bounds__(BLOCK, 1)
slstm_kernel(const float* __restrict__ x,
             const float* __restrict__ Wxh1, const float* __restrict__ bxh1,
             const float* __restrict__ Whh1, const float* __restrict__ bhh1,
             const float* __restrict__ Wxh2, const float* __restrict__ bxh2,
             const float* __restrict__ Whh2, const float* __restrict__ bhh2,
             const float* __restrict__ W1, const float* __restrict__ b1,
             const float* __restrict__ W2, const float* __restrict__ b2,
             const float* __restrict__ W3, const float* __restrict__ b3,
             float* __restrict__ out) {
    extern __shared__ char smem[];
    u64*    wA    = (u64*)(smem + OFF_WA);
    u64*    wB    = (u64*)(smem + OFF_WB);
    u64*    usm   = (u64*)(smem + OFF_U);
    float4* u4f   = (float4*)(smem + OFF_U);
    float*  part  = (float*)(smem + OFF_P);
    float*  gate  = (float*)(smem + OFF_G);
    float*  biasA = (float*)(smem + OFF_BA);
    float*  biasB = (float*)(smem + OFF_BB);

    const int tid  = threadIdx.x;
    const int warp = tid >> 5, lane = tid & 31;
    const int sl = warp >> 1, cg = warp & 1;
    const int bgroup = blockIdx.x >> 5;   // 0..3  (32 batch rows each)
    const int jgroup = blockIdx.x & 31;   // 0..31 (8 hidden idx each)

    unsigned* my_cnt = &bar_cnt4[bgroup][0];
    unsigned* my_gen = &bar_gen4[bgroup][0];
    const unsigned base_g   = ld_acq(my_gen);
    const unsigned base_all = ld_acq(&gbar_gen_all);

    // ---- stage weights (k-pair rows per column) + biases ----
    // smem col c: gate g = c>>3, jl = c&7 -> global gate row = g*256 + jgroup*8 + jl
    {
        float2* wAf = (float2*)wA;
        for (int s = tid; s < 32 * 160; s += BLOCK) {
            int c = s / 160, k2 = s - c * 160;
            int col = (c >> 3) * 256 + jgroup * 8 + (c & 7);
            int k0 = 2 * k2;
            float2 v;
            if (k0 < IN_D) v = *(const float2*)(Wxh1 + col * IN_D + k0);
            else           v = *(const float2*)(Whh1 + col * H_D + (k0 - IN_D));
            wAf[c * 162 + k2] = v;
        }
        float2* wBf = (float2*)wB;
        for (int s = tid; s < 32 * 256; s += BLOCK) {
            int c = s >> 8, k2 = s & 255;
            int col = (c >> 3) * 256 + jgroup * 8 + (c & 7);
            int k0 = 2 * k2;
            float2 v;
            if (k0 < H_D) v = *(const float2*)(Wxh2 + col * H_D + k0);
            else          v = *(const float2*)(Whh2 + col * H_D + (k0 - H_D));
            wBf[c * 258 + k2] = v;
        }
    }
    if (tid < 32) {
        int col = (tid >> 3) * 256 + jgroup * 8 + (tid & 7);
        biasA[tid] = bxh1[col] + bhh1[col];
        biasB[tid] = bxh2[col] + bhh2[col];
    }
    __syncthreads();

    // per-thread cell state (tid<256)
    float c1 = 0.f, m1 = 0.f, n1 = 0.f;
    float c2 = 0.f, m2 = 0.f, n2 = 0.f;
    const int be = tid >> 3, je = tid & 7;
    const int bglob_e = bgroup * 32 + be;
    const int jglob   = jgroup * 8 + je;

    // staging: sb = batch row (0..31), sq = 0..15; u row = sb*129 float4
    const int sb = tid >> 4, sq = tid & 15;
    const int bglobs = bgroup * 32 + sb;
    const float4 zero4 = make_float4(0.f, 0.f, 0.f, 0.f);

    for (int t = 0; t < T_D; ++t) {
        float*       h1cur = h1_buf[t & 1];
        const float* h1old = h1_buf[(t + 1) & 1];
        float*       h2cur = h2_buf[t & 1];
        const float* h2old = h2_buf[(t + 1) & 1];

        // ---- stage u = [x_t | h1_old]  (80 float4 per b) ----
        {
            const float* xrow = x + (bglobs * T_D + t) * IN_D;
            u4f[sb * 129 + sq] = *(const float4*)(xrow + sq * 4);
#pragma unroll
            for (int i = 1; i < 5; ++i) {
                int q = sq + 16 * i;
                float4 v = (t == 0) ? zero4
                         : __ldcg((const float4*)(h1old + bglobs * H_D + (q - 16) * 4));
                u4f[sb * 129 + q] = v;
            }
        }
        __syncthreads();

        gemm_tile<20, WA_S2>(wA, usm, part, sl, cg, lane);
        __syncthreads();
        reduce_gate(part, biasA, gate, tid);
        __syncthreads();

        if (tid < 256) {
            float h1v = cell_update(gate, be, je, c1, m1, n1);
            h1cur[bglob_e * H_D + jglob] = h1v;
        }
        gbar(my_cnt, my_gen, 32u, base_g + (unsigned)t + 1u);   // one barrier per step

        // ---- stage u = [h1_cur | h2_old]  (128 float4 per b) ----
        {
#pragma unroll
            for (int i = 0; i < 4; ++i) {
                int q = sq + 16 * i;
                float4 v = __ldcg((const float4*)(h1cur + bglobs * H_D + q * 4));
                u4f[sb * 129 + q] = v;
            }
#pragma unroll
            for (int i = 4; i < 8; ++i) {
                int q = sq + 16 * i;
                float4 v = (t == 0) ? zero4
                         : __ldcg((const float4*)(h2old + bglobs * H_D + (q - 64) * 4));
                u4f[sb * 129 + q] = v;
            }
        }
        __syncthreads();

        gemm_tile<32, WB_S2>(wB, usm, part, sl, cg, lane);
        __syncthreads();
        reduce_gate(part, biasB, gate, tid);
        __syncthreads();

        if (tid < 256) {
            float h2v = cell_update(gate, be, je, c2, m2, n2);
            h2cur[bglob_e * H_D + jglob] = h2v;
        }
        // next step's group barrier provides the h2 ordering
    }

    gbar(&gbar_cnt_all, &gbar_gen_all, (unsigned)GRID, base_all + 1u);

    // ---- head MLP: one batch row per CTA ----
    {
        const float* h2fin = h2_buf[(T_D - 1) & 1];
        int b = blockIdx.x;
        float* hb = (float*)(smem + OFF_U);
        float* o1 = hb + 256;
        float* o2 = o1 + 128;
        float* pr = o2 + 64;
        for (int i = tid; i < H_D; i += BLOCK) hb[i] = __ldcg(h2fin + b * H_D + i);
        __syncthreads();
        if (tid < 128) {
            const float* w = W1 + tid * H_D;
            float s = b1[tid];
#pragma unroll 4
            for (int k = 0; k < H_D; k += 4) {
                float4 hv = *(const float4*)(hb + k);
                float4 wv = *(const float4*)(w + k);
                s += hv.x * wv.x + hv.y * wv.y + hv.z * wv.z + hv.w * wv.w;
            }
            o1[tid] = fmaxf(s, 0.f);
        }
        __syncthreads();
        if (tid < 64) {
            const float* w = W2 + tid * 128;
            float s = b2[tid];
#pragma unroll 4
            for (int k = 0; k < 128; ++k) s += o1[k] * w[k];
            o2[tid] = fmaxf(s, 0.f);
        }
        __syncthreads();
        if (tid < 64) pr[tid] = o2[tid] * W3[tid];
        __syncthreads();
        if (tid == 0) {
            float s = b3[0];
            for (int k = 0; k < 64; ++k) s += pr[k];
            out[b] = s;
        }
    }
}

extern "C" void kernel_launch(void* const* d_in, const int* in_sizes, int n_in,
                              void* d_out, int out_size) {
    const float* x    = (const float*)d_in[0];
    const float* Wxh1 = (const float*)d_in[1];
    const float* bxh1 = (const float*)d_in[2];
    const float* Whh1 = (const float*)d_in[3];
    const float* bhh1 = (const float*)d_in[4];
    const float* Wxh2 = (const float*)d_in[5];
    const float* bxh2 = (const float*)d_in[6];
    const float* Whh2 = (const float*)d_in[7];
    const float* bhh2 = (const float*)d_in[8];
    const float* W1   = (const float*)d_in[9];
    const float* b1   = (const float*)d_in[10];
    const float* W2   = (const float*)d_in[11];
    const float* b2   = (const float*)d_in[12];
    const float* W3   = (const float*)d_in[13];
    const float* b3   = (const float*)d_in[14];

    cudaFuncSetAttribute(slstm_kernel,
                         cudaFuncAttributeMaxDynamicSharedMemorySize, SMEM_BYTES);
    slstm_kernel<<<GRID, BLOCK, SMEM_BYTES>>>(x, Wxh1, bxh1, Whh1, bhh1,
                                              Wxh2, bxh2, Whh2, bhh2,
                                              W1, b1, W2, b2, W3, b3,
                                              (float*)d_out);
}